// round 3
// baseline (speedup 1.0000x reference)
#include <cuda_runtime.h>
#include <cstdint>

#define N_NODES 100000
#define N_EDGES 3200000
#define D_IN    256
#define D_HID   256
#define D_OUT   128

// ---------------- scratch (static device globals; no allocation) ----------------
__device__ float g_h1  [(size_t)N_NODES * D_HID];   // X @ W1
__device__ float g_agg1[(size_t)N_NODES * D_HID];   // aggregated layer-1 (pre bias/relu)
__device__ float g_h2  [(size_t)N_NODES * D_OUT];   // relu(agg1+b1) @ W2
__device__ int   g_src [N_EDGES];
__device__ int   g_dst [N_EDGES];
__device__ float g_norm[N_EDGES];
__device__ int   g_deg [N_NODES];
__device__ float g_dinv [N_NODES];
__device__ float g_dinv2[N_NODES];

// ---------------- degree / norm prep ----------------
__global__ void k_init_deg(int n) {
    int i = blockIdx.x * blockDim.x + threadIdx.x;
    if (i < n) g_deg[i] = 1;   // self loop
}

// edge_index is int32 (JAX default x64-disabled: jnp.int64 request silently yields int32)
__global__ void k_prep_edges(const int* __restrict__ ei, int nE) {
    int e = blockIdx.x * blockDim.x + threadIdx.x;
    if (e >= nE) return;
    int s = ei[e];
    int d = ei[nE + e];
    g_src[e] = s;
    g_dst[e] = d;
    atomicAdd(&g_deg[d], 1);
}

__global__ void k_dinv(int n) {
    int i = blockIdx.x * blockDim.x + threadIdx.x;
    if (i >= n) return;
    float r = rsqrtf((float)g_deg[i]);   // deg >= 1 always (self loop)
    g_dinv[i]  = r;
    g_dinv2[i] = r * r;
}

__global__ void k_norm(int nE) {
    int e = blockIdx.x * blockDim.x + threadIdx.x;
    if (e >= nE) return;
    g_norm[e] = g_dinv[g_src[e]] * g_dinv[g_dst[e]];
}

// ---------------- SGEMM: C = A[M,256] @ W[256,N], fused epilogue ----------------
// Epilogue writes H (raw gemm result) and G = H * dinv2[row] (self-loop init of the
// aggregation buffer). If RELU_BIAS, A elements are transformed relu(a + bias[k]) on load.
template<int N, bool RELU_BIAS>
__global__ __launch_bounds__(256, 2)
void sgemm_k256(const float* __restrict__ A, const float* __restrict__ W,
                const float* __restrict__ bias,
                float* __restrict__ H, float* __restrict__ G,
                int M)
{
    constexpr int K = 256;
    __shared__ float As[8][128];
    __shared__ float Bs[8][128];

    const int bm  = blockIdx.y * 128;
    const int bn  = blockIdx.x * 128;
    const int tid = threadIdx.x;

    const int ar  = tid >> 1;         // 0..127 (A tile row)
    const int ac  = (tid & 1) * 4;    // 0 or 4 (A tile k-offset)
    const int brw = tid >> 5;         // 0..7   (B tile k-row)
    const int bcl = (tid & 31) * 4;   // 0..124 (B tile col)
    const int tx  = tid & 15;
    const int ty  = tid >> 4;

    float acc[8][8] = {};

    for (int k0 = 0; k0 < K; k0 += 8) {
        // load A tile (128 rows x 8 k), transpose into As[k][m]
        float4 av = make_float4(0.f, 0.f, 0.f, 0.f);
        int gm = bm + ar;
        if (gm < M)
            av = *(const float4*)(A + (size_t)gm * K + k0 + ac);
        if (RELU_BIAS) {
            av.x = fmaxf(av.x + bias[k0 + ac + 0], 0.f);
            av.y = fmaxf(av.y + bias[k0 + ac + 1], 0.f);
            av.z = fmaxf(av.z + bias[k0 + ac + 2], 0.f);
            av.w = fmaxf(av.w + bias[k0 + ac + 3], 0.f);
        }
        As[ac + 0][ar] = av.x;
        As[ac + 1][ar] = av.y;
        As[ac + 2][ar] = av.z;
        As[ac + 3][ar] = av.w;

        // load B tile (8 k x 128 n)
        *(float4*)&Bs[brw][bcl] = *(const float4*)(W + (size_t)(k0 + brw) * N + bn + bcl);

        __syncthreads();

        #pragma unroll
        for (int kk = 0; kk < 8; kk++) {
            float a0[8], b0[8];
            #pragma unroll
            for (int i = 0; i < 8; i++) a0[i] = As[kk][ty * 8 + i];
            #pragma unroll
            for (int j = 0; j < 8; j++) b0[j] = Bs[kk][tx * 8 + j];
            #pragma unroll
            for (int i = 0; i < 8; i++)
                #pragma unroll
                for (int j = 0; j < 8; j++)
                    acc[i][j] += a0[i] * b0[j];
        }
        __syncthreads();
    }

    #pragma unroll
    for (int i = 0; i < 8; i++) {
        int gm = bm + ty * 8 + i;
        if (gm >= M) continue;
        float dv = g_dinv2[gm];
        #pragma unroll
        for (int j = 0; j < 8; j += 4) {
            int gn = bn + tx * 8 + j;
            float4 v = make_float4(acc[i][j], acc[i][j+1], acc[i][j+2], acc[i][j+3]);
            *(float4*)(H + (size_t)gm * N + gn) = v;
            float4 g = make_float4(v.x * dv, v.y * dv, v.z * dv, v.w * dv);
            *(float4*)(G + (size_t)gm * N + gn) = g;
        }
    }
}

// ---------------- edge aggregation: agg[dst] += h[src] * norm ----------------
// C = number of float4 chunks per node row (64 for D=256, 32 for D=128)
// Scalar atomicAdd with unused return -> REDG.E.ADD.F32 (no-return L2 reduction).
template<int C>
__global__ void k_agg(const float4* __restrict__ h, float* __restrict__ agg, int nE)
{
    int t = blockIdx.x * blockDim.x + threadIdx.x;
    int e = t / C;
    int c = t % C;
    if (e >= nE) return;
    int   s = __ldg(g_src + e);
    int   d = __ldg(g_dst + e);
    float n = __ldg(g_norm + e);
    float4 v = h[(size_t)s * C + c];
    float* p = agg + (size_t)d * (C * 4) + c * 4;
    atomicAdd(p + 0, v.x * n);
    atomicAdd(p + 1, v.y * n);
    atomicAdd(p + 2, v.z * n);
    atomicAdd(p + 3, v.w * n);
}

// ---------------- final: out = sigmoid(out + b2) ----------------
__global__ void k_final(float* __restrict__ out, const float* __restrict__ b2, int M)
{
    int t = blockIdx.x * blockDim.x + threadIdx.x;   // indexes float4 over [M, 128]
    if (t >= M * (D_OUT / 4)) return;
    int c = t & (D_OUT / 4 - 1);
    float4 v = ((float4*)out)[t];
    float4 b = ((const float4*)b2)[c];
    v.x = 1.f / (1.f + expf(-(v.x + b.x)));
    v.y = 1.f / (1.f + expf(-(v.y + b.y)));
    v.z = 1.f / (1.f + expf(-(v.z + b.z)));
    v.w = 1.f / (1.f + expf(-(v.w + b.w)));
    ((float4*)out)[t] = v;
}

// ---------------- launch ----------------
extern "C" void kernel_launch(void* const* d_in, const int* in_sizes, int n_in,
                              void* d_out, int out_size)
{
    const float* x  = (const float*)d_in[0];
    const int*   ei = (const int*)d_in[1];      // int32 edge_index [2, E]
    const float* W1 = (const float*)d_in[2];
    const float* b1 = (const float*)d_in[3];
    const float* W2 = (const float*)d_in[4];
    const float* b2 = (const float*)d_in[5];
    float*       out = (float*)d_out;

    const int M  = N_NODES;
    const int nE = N_EDGES;

    float *h1, *agg1, *h2;
    cudaGetSymbolAddress((void**)&h1,   g_h1);
    cudaGetSymbolAddress((void**)&agg1, g_agg1);
    cudaGetSymbolAddress((void**)&h2,   g_h2);

    // degree + norm prep
    k_init_deg  <<<(M  + 255) / 256, 256>>>(M);
    k_prep_edges<<<(nE + 255) / 256, 256>>>(ei, nE);
    k_dinv      <<<(M  + 255) / 256, 256>>>(M);
    k_norm      <<<(nE + 255) / 256, 256>>>(nE);

    dim3 g1(D_HID / 128, (M + 127) / 128);
    dim3 g2(D_OUT / 128, (M + 127) / 128);

    // layer 1: h1 = x @ W1 ; agg1 initialized with self-loop term h1*dinv2
    sgemm_k256<D_HID, false><<<g1, 256>>>(x, W1, nullptr, h1, agg1, M);

    // agg1[dst] += h1[src] * norm   (D=256 -> 64 float4 chunks)
    {
        long long work = (long long)nE * 64;
        k_agg<64><<<(unsigned)((work + 255) / 256), 256>>>((const float4*)h1, agg1, nE);
    }

    // layer 2: h2 = relu(agg1 + b1) @ W2 ; d_out initialized with self-loop term h2*dinv2
    sgemm_k256<D_OUT, true><<<g2, 256>>>(agg1, W2, b1, h2, out, M);

    // out[dst] += h2[src] * norm   (D=128 -> 32 float4 chunks)
    {
        long long work = (long long)nE * 32;
        k_agg<32><<<(unsigned)((work + 255) / 256), 256>>>((const float4*)h2, out, nE);
    }

    // out = sigmoid(out + b2)
    k_final<<<(M * (D_OUT / 4) + 255) / 256, 256>>>(out, b2, M);
}

// round 4
// speedup vs baseline: 2.5273x; 2.5273x over previous
#include <cuda_runtime.h>
#include <cstdint>

#define N_NODES 100000
#define N_EDGES 3200000
#define D_IN    256
#define D_HID   256
#define D_OUT   128

// ---------------- scratch (static device globals; no allocation) ----------------
__device__ float g_h1  [(size_t)N_NODES * D_HID];   // X @ W1
__device__ float g_agg1[(size_t)N_NODES * D_HID];   // relu(A_norm @ h1 + b1)
__device__ float g_h2  [(size_t)N_NODES * D_OUT];   // agg1 @ W2
__device__ int   g_csrc [N_EDGES];                  // CSR: src node per edge (dst-sorted)
__device__ float g_cnorm[N_EDGES];                  // CSR: edge norm
__device__ int   g_rowptr[N_NODES + 1];
__device__ int   g_cursor[N_NODES];
__device__ int   g_cnt   [N_NODES];                 // incoming-edge count (no self loop)
__device__ float g_dinv  [N_NODES];
__device__ float g_dinv2 [N_NODES];

// ---------------- prep ----------------
__global__ void k_zero_cnt(int n) {
    int i = blockIdx.x * blockDim.x + threadIdx.x;
    if (i < n) g_cnt[i] = 0;
}

// edge_index is int32 (JAX x64 disabled)
__global__ void k_count(const int* __restrict__ ei, int nE) {
    int e = blockIdx.x * blockDim.x + threadIdx.x;
    if (e >= nE) return;
    atomicAdd(&g_cnt[ei[nE + e]], 1);
}

// single-block exclusive scan over g_cnt -> g_rowptr, init g_cursor
__global__ void k_scan(int n) {
    const int T = 1024;
    __shared__ int s[T];
    int t = threadIdx.x;
    int items = (n + T - 1) / T;
    int base = t * items;

    int sum = 0;
    for (int j = 0; j < items; j++) {
        int idx = base + j;
        if (idx < n) sum += g_cnt[idx];
    }
    s[t] = sum;
    __syncthreads();
    for (int off = 1; off < T; off <<= 1) {
        int v = (t >= off) ? s[t - off] : 0;
        __syncthreads();
        s[t] += v;
        __syncthreads();
    }
    int run = s[t] - sum;   // exclusive prefix
    for (int j = 0; j < items; j++) {
        int idx = base + j;
        if (idx < n) {
            g_rowptr[idx] = run;
            g_cursor[idx] = run;
            run += g_cnt[idx];
        }
    }
    if (t == T - 1) g_rowptr[n] = s[T - 1];
}

__global__ void k_dinv(int n) {
    int i = blockIdx.x * blockDim.x + threadIdx.x;
    if (i >= n) return;
    float r = rsqrtf((float)(g_cnt[i] + 1));   // +1 self loop
    g_dinv[i]  = r;
    g_dinv2[i] = r * r;
}

__global__ void k_fill(const int* __restrict__ ei, int nE) {
    int e = blockIdx.x * blockDim.x + threadIdx.x;
    if (e >= nE) return;
    int s = ei[e];
    int d = ei[nE + e];
    int pos = atomicAdd(&g_cursor[d], 1);
    g_csrc[pos]  = s;
    g_cnorm[pos] = g_dinv[s] * g_dinv[d];
}

// ---------------- SGEMM: H = A[M,256] @ W[256,N] ----------------
template<int N>
__global__ __launch_bounds__(256, 2)
void sgemm_k256(const float* __restrict__ A, const float* __restrict__ W,
                float* __restrict__ H, int M)
{
    constexpr int K = 256;
    __shared__ float As[8][128];
    __shared__ float Bs[8][128];

    const int bm  = blockIdx.y * 128;
    const int bn  = blockIdx.x * 128;
    const int tid = threadIdx.x;

    const int ar  = tid >> 1;
    const int ac  = (tid & 1) * 4;
    const int brw = tid >> 5;
    const int bcl = (tid & 31) * 4;
    const int tx  = tid & 15;
    const int ty  = tid >> 4;

    float acc[8][8] = {};

    for (int k0 = 0; k0 < K; k0 += 8) {
        float4 av = make_float4(0.f, 0.f, 0.f, 0.f);
        int gm = bm + ar;
        if (gm < M)
            av = *(const float4*)(A + (size_t)gm * K + k0 + ac);
        As[ac + 0][ar] = av.x;
        As[ac + 1][ar] = av.y;
        As[ac + 2][ar] = av.z;
        As[ac + 3][ar] = av.w;

        *(float4*)&Bs[brw][bcl] = *(const float4*)(W + (size_t)(k0 + brw) * N + bn + bcl);

        __syncthreads();

        #pragma unroll
        for (int kk = 0; kk < 8; kk++) {
            float a0[8], b0[8];
            #pragma unroll
            for (int i = 0; i < 8; i++) a0[i] = As[kk][ty * 8 + i];
            #pragma unroll
            for (int j = 0; j < 8; j++) b0[j] = Bs[kk][tx * 8 + j];
            #pragma unroll
            for (int i = 0; i < 8; i++)
                #pragma unroll
                for (int j = 0; j < 8; j++)
                    acc[i][j] += a0[i] * b0[j];
        }
        __syncthreads();
    }

    #pragma unroll
    for (int i = 0; i < 8; i++) {
        int gm = bm + ty * 8 + i;
        if (gm >= M) continue;
        #pragma unroll
        for (int j = 0; j < 8; j += 4) {
            int gn = bn + tx * 8 + j;
            *(float4*)(H + (size_t)gm * N + gn) =
                make_float4(acc[i][j], acc[i][j+1], acc[i][j+2], acc[i][j+3]);
        }
    }
}

// ---------------- CSR aggregation, fused self-loop + bias + activation --------
// One block per node, one thread per feature. ACT: 0 = relu, 1 = sigmoid.
template<int D, int ACT>
__global__ __launch_bounds__(D)
void k_agg_csr(const float* __restrict__ h, const float* __restrict__ bias,
               float* __restrict__ out)
{
    int i = blockIdx.x;
    int t = threadIdx.x;
    int beg = g_rowptr[i];
    int end = g_rowptr[i + 1];

    float acc = g_dinv2[i] * __ldg(h + (size_t)i * D + t);   // self loop

    int e = beg;
    for (; e + 4 <= end; e += 4) {
        int   s0 = __ldg(g_csrc + e);
        int   s1 = __ldg(g_csrc + e + 1);
        int   s2 = __ldg(g_csrc + e + 2);
        int   s3 = __ldg(g_csrc + e + 3);
        float n0 = __ldg(g_cnorm + e);
        float n1 = __ldg(g_cnorm + e + 1);
        float n2 = __ldg(g_cnorm + e + 2);
        float n3 = __ldg(g_cnorm + e + 3);
        float v0 = __ldg(h + (size_t)s0 * D + t);
        float v1 = __ldg(h + (size_t)s1 * D + t);
        float v2 = __ldg(h + (size_t)s2 * D + t);
        float v3 = __ldg(h + (size_t)s3 * D + t);
        acc += n0 * v0;
        acc += n1 * v1;
        acc += n2 * v2;
        acc += n3 * v3;
    }
    for (; e < end; e++)
        acc += __ldg(g_cnorm + e) * __ldg(h + (size_t)__ldg(g_csrc + e) * D + t);

    acc += bias[t];
    if (ACT == 0)
        acc = fmaxf(acc, 0.f);
    else
        acc = 1.f / (1.f + expf(-acc));
    out[(size_t)i * D + t] = acc;
}

// ---------------- launch ----------------
extern "C" void kernel_launch(void* const* d_in, const int* in_sizes, int n_in,
                              void* d_out, int out_size)
{
    const float* x  = (const float*)d_in[0];
    const int*   ei = (const int*)d_in[1];      // int32 edge_index [2, E]
    const float* W1 = (const float*)d_in[2];
    const float* b1 = (const float*)d_in[3];
    const float* W2 = (const float*)d_in[4];
    const float* b2 = (const float*)d_in[5];
    float*       out = (float*)d_out;

    const int M  = N_NODES;
    const int nE = N_EDGES;

    float *h1, *agg1, *h2;
    cudaGetSymbolAddress((void**)&h1,   g_h1);
    cudaGetSymbolAddress((void**)&agg1, g_agg1);
    cudaGetSymbolAddress((void**)&h2,   g_h2);

    // CSR + norm prep
    k_zero_cnt<<<(M  + 255) / 256, 256>>>(M);
    k_count   <<<(nE + 255) / 256, 256>>>(ei, nE);
    k_scan    <<<1, 1024>>>(M);
    k_dinv    <<<(M  + 255) / 256, 256>>>(M);
    k_fill    <<<(nE + 255) / 256, 256>>>(ei, nE);

    dim3 g1(D_HID / 128, (M + 127) / 128);
    dim3 g2(D_OUT / 128, (M + 127) / 128);

    // layer 1
    sgemm_k256<D_HID><<<g1, 256>>>(x, W1, h1, M);
    k_agg_csr<D_HID, 0><<<M, D_HID>>>(h1, b1, agg1);

    // layer 2
    sgemm_k256<D_OUT><<<g2, 256>>>(agg1, W2, h2, M);
    k_agg_csr<D_OUT, 1><<<M, D_OUT>>>(h2, b2, out);
}

// round 5
// speedup vs baseline: 4.4353x; 1.7550x over previous
#include <cuda_runtime.h>
#include <cstdint>

#define N_NODES 100000
#define N_EDGES 3200000
#define D_IN    256
#define D_HID   256
#define D_OUT   128

// ---------------- scratch (static device globals; no allocation) ----------------
__device__ float g_h1  [(size_t)N_NODES * D_HID];   // X @ W1
__device__ float g_agg1[(size_t)N_NODES * D_HID];   // relu(A_norm @ h1 + b1)
__device__ float g_h2  [(size_t)N_NODES * D_OUT];   // agg1 @ W2
__device__ int   g_csrc [N_EDGES];                  // CSR: src node per edge (dst-sorted)
__device__ float g_cnorm[N_EDGES];                  // CSR: edge norm
__device__ int   g_rowptr[N_NODES + 1];
__device__ int   g_cursor[N_NODES];
__device__ int   g_cnt   [N_NODES];                 // incoming-edge count (no self loop)
__device__ float g_dinv  [N_NODES];
__device__ float g_dinv2 [N_NODES];

// ---------------- prep ----------------
__global__ void k_zero_cnt(int n) {
    int i = blockIdx.x * blockDim.x + threadIdx.x;
    if (i < n) g_cnt[i] = 0;
}

// edge_index is int32 (JAX x64 disabled)
__global__ void k_count(const int* __restrict__ ei, int nE) {
    int e = blockIdx.x * blockDim.x + threadIdx.x;
    if (e >= nE) return;
    atomicAdd(&g_cnt[ei[nE + e]], 1);
}

// single-block exclusive scan over g_cnt -> g_rowptr, init g_cursor
__global__ void k_scan(int n) {
    const int T = 1024;
    __shared__ int s[T];
    int t = threadIdx.x;
    int items = (n + T - 1) / T;
    int base = t * items;

    int sum = 0;
    for (int j = 0; j < items; j++) {
        int idx = base + j;
        if (idx < n) sum += g_cnt[idx];
    }
    s[t] = sum;
    __syncthreads();
    for (int off = 1; off < T; off <<= 1) {
        int v = (t >= off) ? s[t - off] : 0;
        __syncthreads();
        s[t] += v;
        __syncthreads();
    }
    int run = s[t] - sum;   // exclusive prefix
    for (int j = 0; j < items; j++) {
        int idx = base + j;
        if (idx < n) {
            g_rowptr[idx] = run;
            g_cursor[idx] = run;
            run += g_cnt[idx];
        }
    }
    if (t == T - 1) g_rowptr[n] = s[T - 1];
}

__global__ void k_dinv(int n) {
    int i = blockIdx.x * blockDim.x + threadIdx.x;
    if (i >= n) return;
    float r = rsqrtf((float)(g_cnt[i] + 1));   // +1 self loop
    g_dinv[i]  = r;
    g_dinv2[i] = r * r;
}

__global__ void k_fill(const int* __restrict__ ei, int nE) {
    int e = blockIdx.x * blockDim.x + threadIdx.x;
    if (e >= nE) return;
    int s = ei[e];
    int d = ei[nE + e];
    int pos = atomicAdd(&g_cursor[d], 1);
    g_csrc[pos]  = s;
    g_cnorm[pos] = g_dinv[s] * g_dinv[d];
}

// ---------------- TF32 tensor-core GEMM: H = A[M,256] @ W[256,N] ----------------
// Block tile 128x128, BK=16, 8 warps (2Mx4N), warp tile 64x32 (4x4 m16n8k8 atoms).
// smem stride 136 floats -> fragment LDS (tig*136 + g) is bank-conflict-free.
__device__ __forceinline__ uint32_t f2tf32(float f) {
    uint32_t r;
    asm("cvt.rna.tf32.f32 %0, %1;" : "=r"(r) : "f"(f));
    return r;
}

template<int N>
__global__ __launch_bounds__(256, 2)
void gemm_tf32(const float* __restrict__ A, const float* __restrict__ W,
               float* __restrict__ H, int M)
{
    constexpr int K  = 256;
    constexpr int BK = 16;
    constexpr int ST = 136;                 // smem row stride (floats)
    __shared__ float As[BK * ST];           // [k][m] transposed
    __shared__ float Bs[BK * ST];           // [k][n]

    const int tid   = threadIdx.x;
    const int lane  = tid & 31;
    const int wid   = tid >> 5;
    const int warpM = wid & 1;              // 0..1
    const int warpN = wid >> 1;             // 0..3
    const int g     = lane >> 2;            // groupID 0..7
    const int tig   = lane & 3;             // thread-in-group 0..3

    const int bm = blockIdx.y * 128;
    const int bn = blockIdx.x * 128;

    float c[4][4][4];                       // [am][an][4]
    #pragma unroll
    for (int am = 0; am < 4; am++)
        #pragma unroll
        for (int an = 0; an < 4; an++)
            #pragma unroll
            for (int r = 0; r < 4; r++) c[am][an][r] = 0.f;

    for (int k0 = 0; k0 < K; k0 += BK) {
        // ---- load A tile (128 m x 16 k), transpose to As[k][m], tf32-round ----
        #pragma unroll
        for (int it = 0; it < 2; it++) {
            int idx = tid + it * 256;       // 0..511
            int row = idx >> 2;             // 0..127
            int kq  = (idx & 3) * 4;        // 0,4,8,12
            float4 av = make_float4(0.f, 0.f, 0.f, 0.f);
            int gm = bm + row;
            if (gm < M)
                av = *(const float4*)(A + (size_t)gm * K + k0 + kq);
            As[(kq + 0) * ST + row] = __uint_as_float(f2tf32(av.x));
            As[(kq + 1) * ST + row] = __uint_as_float(f2tf32(av.y));
            As[(kq + 2) * ST + row] = __uint_as_float(f2tf32(av.z));
            As[(kq + 3) * ST + row] = __uint_as_float(f2tf32(av.w));
        }
        // ---- load B tile (16 k x 128 n) ----
        #pragma unroll
        for (int it = 0; it < 2; it++) {
            int idx  = tid + it * 256;
            int krow = idx >> 5;            // 0..15
            int nq   = (idx & 31) * 4;      // 0..124
            float4 bv = *(const float4*)(W + (size_t)(k0 + krow) * N + bn + nq);
            float4 bt;
            bt.x = __uint_as_float(f2tf32(bv.x));
            bt.y = __uint_as_float(f2tf32(bv.y));
            bt.z = __uint_as_float(f2tf32(bv.z));
            bt.w = __uint_as_float(f2tf32(bv.w));
            *(float4*)&Bs[krow * ST + nq] = bt;
        }
        __syncthreads();

        #pragma unroll
        for (int kk = 0; kk < BK; kk += 8) {
            // A fragments: 4 m-atoms
            uint32_t af[4][4];
            #pragma unroll
            for (int am = 0; am < 4; am++) {
                int m0 = warpM * 64 + am * 16 + g;
                af[am][0] = __float_as_uint(As[(kk + tig)     * ST + m0]);
                af[am][1] = __float_as_uint(As[(kk + tig)     * ST + m0 + 8]);
                af[am][2] = __float_as_uint(As[(kk + tig + 4) * ST + m0]);
                af[am][3] = __float_as_uint(As[(kk + tig + 4) * ST + m0 + 8]);
            }
            // B fragments: 4 n-atoms
            uint32_t bf[4][2];
            #pragma unroll
            for (int an = 0; an < 4; an++) {
                int n0 = warpN * 32 + an * 8 + g;
                bf[an][0] = __float_as_uint(Bs[(kk + tig)     * ST + n0]);
                bf[an][1] = __float_as_uint(Bs[(kk + tig + 4) * ST + n0]);
            }
            #pragma unroll
            for (int am = 0; am < 4; am++)
                #pragma unroll
                for (int an = 0; an < 4; an++) {
                    asm volatile(
                        "mma.sync.aligned.m16n8k8.row.col.f32.tf32.tf32.f32 "
                        "{%0,%1,%2,%3}, {%4,%5,%6,%7}, {%8,%9}, {%0,%1,%2,%3};"
                        : "+f"(c[am][an][0]), "+f"(c[am][an][1]),
                          "+f"(c[am][an][2]), "+f"(c[am][an][3])
                        : "r"(af[am][0]), "r"(af[am][1]), "r"(af[am][2]), "r"(af[am][3]),
                          "r"(bf[an][0]), "r"(bf[an][1]));
                }
        }
        __syncthreads();
    }

    // ---- epilogue: c0,c1 at (row, col..col+1), c2,c3 at (row+8, ...) ----
    #pragma unroll
    for (int am = 0; am < 4; am++) {
        int row = bm + warpM * 64 + am * 16 + g;
        #pragma unroll
        for (int an = 0; an < 4; an++) {
            int col = bn + warpN * 32 + an * 8 + tig * 2;
            if (row < M)
                *(float2*)(H + (size_t)row * N + col) =
                    make_float2(c[am][an][0], c[am][an][1]);
            if (row + 8 < M)
                *(float2*)(H + (size_t)(row + 8) * N + col) =
                    make_float2(c[am][an][2], c[am][an][3]);
        }
    }
}

// ---------------- CSR aggregation, fused self-loop + bias + activation --------
// float4 lanes: L = D/4 lanes per node, NPB nodes per 256-thread block.
// ACT: 0 = relu, 1 = sigmoid.
template<int D, int ACT>
__global__ __launch_bounds__(256)
void k_agg_csr(const float* __restrict__ h, const float* __restrict__ bias,
               float* __restrict__ out)
{
    constexpr int L   = D / 4;      // float4 lanes per node (64 or 32)
    constexpr int NPB = 256 / L;    // nodes per block (4 or 8)

    int grp  = threadIdx.x / L;
    int lane = threadIdx.x % L;
    int i = blockIdx.x * NPB + grp;
    if (i >= N_NODES) return;

    const float4* hv = (const float4*)h;
    int beg = g_rowptr[i];
    int end = g_rowptr[i + 1];

    float4 sv = __ldg(hv + (size_t)i * L + lane);
    float dv  = g_dinv2[i];
    float4 acc = make_float4(sv.x * dv, sv.y * dv, sv.z * dv, sv.w * dv);

    int e = beg;
    for (; e + 4 <= end; e += 4) {
        int   s0 = __ldg(g_csrc + e);
        int   s1 = __ldg(g_csrc + e + 1);
        int   s2 = __ldg(g_csrc + e + 2);
        int   s3 = __ldg(g_csrc + e + 3);
        float n0 = __ldg(g_cnorm + e);
        float n1 = __ldg(g_cnorm + e + 1);
        float n2 = __ldg(g_cnorm + e + 2);
        float n3 = __ldg(g_cnorm + e + 3);
        float4 v0 = __ldg(hv + (size_t)s0 * L + lane);
        float4 v1 = __ldg(hv + (size_t)s1 * L + lane);
        float4 v2 = __ldg(hv + (size_t)s2 * L + lane);
        float4 v3 = __ldg(hv + (size_t)s3 * L + lane);
        acc.x += n0 * v0.x; acc.y += n0 * v0.y; acc.z += n0 * v0.z; acc.w += n0 * v0.w;
        acc.x += n1 * v1.x; acc.y += n1 * v1.y; acc.z += n1 * v1.z; acc.w += n1 * v1.w;
        acc.x += n2 * v2.x; acc.y += n2 * v2.y; acc.z += n2 * v2.z; acc.w += n2 * v2.w;
        acc.x += n3 * v3.x; acc.y += n3 * v3.y; acc.z += n3 * v3.z; acc.w += n3 * v3.w;
    }
    for (; e < end; e++) {
        float n = __ldg(g_cnorm + e);
        float4 v = __ldg(hv + (size_t)__ldg(g_csrc + e) * L + lane);
        acc.x += n * v.x; acc.y += n * v.y; acc.z += n * v.z; acc.w += n * v.w;
    }

    const float4* bv = (const float4*)bias;
    float4 b = __ldg(bv + lane);
    acc.x += b.x; acc.y += b.y; acc.z += b.z; acc.w += b.w;
    if (ACT == 0) {
        acc.x = fmaxf(acc.x, 0.f); acc.y = fmaxf(acc.y, 0.f);
        acc.z = fmaxf(acc.z, 0.f); acc.w = fmaxf(acc.w, 0.f);
    } else {
        acc.x = 1.f / (1.f + expf(-acc.x));
        acc.y = 1.f / (1.f + expf(-acc.y));
        acc.z = 1.f / (1.f + expf(-acc.z));
        acc.w = 1.f / (1.f + expf(-acc.w));
    }
    ((float4*)out)[(size_t)i * L + lane] = acc;
}

// ---------------- launch ----------------
extern "C" void kernel_launch(void* const* d_in, const int* in_sizes, int n_in,
                              void* d_out, int out_size)
{
    const float* x  = (const float*)d_in[0];
    const int*   ei = (const int*)d_in[1];      // int32 edge_index [2, E]
    const float* W1 = (const float*)d_in[2];
    const float* b1 = (const float*)d_in[3];
    const float* W2 = (const float*)d_in[4];
    const float* b2 = (const float*)d_in[5];
    float*       out = (float*)d_out;

    const int M  = N_NODES;
    const int nE = N_EDGES;

    float *h1, *agg1, *h2;
    cudaGetSymbolAddress((void**)&h1,   g_h1);
    cudaGetSymbolAddress((void**)&agg1, g_agg1);
    cudaGetSymbolAddress((void**)&h2,   g_h2);

    // CSR + norm prep
    k_zero_cnt<<<(M  + 255) / 256, 256>>>(M);
    k_count   <<<(nE + 255) / 256, 256>>>(ei, nE);
    k_scan    <<<1, 1024>>>(M);
    k_dinv    <<<(M  + 255) / 256, 256>>>(M);
    k_fill    <<<(nE + 255) / 256, 256>>>(ei, nE);

    dim3 g1(D_HID / 128, (M + 127) / 128);
    dim3 g2(D_OUT / 128, (M + 127) / 128);

    // layer 1
    gemm_tf32<D_HID><<<g1, 256>>>(x, W1, h1, M);
    k_agg_csr<D_HID, 0><<<(M + 3) / 4, 256>>>(h1, b1, agg1);

    // layer 2
    gemm_tf32<D_OUT><<<g2, 256>>>(agg1, W2, h2, M);
    k_agg_csr<D_OUT, 1><<<(M + 7) / 8, 256>>>(h2, b2, out);
}